// round 4
// baseline (speedup 1.0000x reference)
#include <cuda_runtime.h>

// LeakyCascade: s[t] = a*s[t-1] + (1-a)*x[t] = a*(s-x)+x,  a = exp(-dt/tau_m)
// B=8, T=4096, D=256, M=8.
// Blocked scan over T. Each THREAD owns one d-lane (float4) and ALL 8 m
// states in registers, so x is loaded once per t (no 8x L1 redundancy).

#define BB 8
#define TT 4096
#define DD 256
#define MM 8
#define CC 128           // chunks along T
#define LL (TT / CC)     // 32 steps per chunk
#define D4 (DD / 4)      // 64 float4 lanes
#define GG 2             // chunks per block
#define NTHR (GG * D4)   // 128 threads: tid/64 = chunk-in-block, tid%64 = lane

// Scratch (static device globals — no allocation in kernel_launch)
// Layout [B][C][M][D]: phase2 (thread=(b,m,d)) reads coalesced in d.
__device__ float g_send[BB * CC * MM * DD];  // local chunk end-states (8 MB)
__device__ float g_sin [BB * CC * MM * DD];  // true chunk start-states (8 MB)
__device__ float g_A   [BB * CC * MM];       // per-chunk total decay

// ---------------------------------------------------------------------------
// Alpha staging: per chunk-group, compute dt (32 t-steps) and alpha[m][i].
// ---------------------------------------------------------------------------
__device__ __forceinline__ void stage_alpha(
    const float* __restrict__ drow, const float* __restrict__ tau,
    int g, int lane, int t0,
    float (*sdt)[LL], float (*sal)[MM][LL], float* sdsum)
{
    if (lane < LL) {
        const int t = t0 + lane;
        float dt = (t == 0) ? 0.0f : fmaxf(drow[t] - drow[t - 1], 0.0f);
        sdt[g][lane] = dt;
        float dsum = dt;
        #pragma unroll
        for (int off = 16; off > 0; off >>= 1)
            dsum += __shfl_down_sync(0xffffffffu, dsum, off);
        if (lane == 0) sdsum[g] = dsum;
    }
    __syncthreads();
    #pragma unroll
    for (int k = 0; k < 4; k++) {                 // 64 threads x 4 = 256 alphas
        const int j = lane + 64 * k;
        const int m = j >> 5, i = j & 31;
        sal[g][m][i] = expf(-sdt[g][i] / tau[m]);
    }
    __syncthreads();
}

// ---------------------------------------------------------------------------
// Phase 1: per-chunk local scan from s=0 ; emit s_end and chunk decay A.
// grid = (CC/GG, B) = (64, 8), block = 128
// ---------------------------------------------------------------------------
__global__ void __launch_bounds__(NTHR) lc_phase1(
    const float* __restrict__ x, const float* __restrict__ delta,
    const float* __restrict__ tau)
{
    const int b = blockIdx.y;
    const int tid = threadIdx.x;
    const int g = tid >> 6, lane = tid & 63;
    const int c = blockIdx.x * GG + g;
    const int t0 = c * LL;

    __shared__ float sdt[GG][LL];
    __shared__ float sal[GG][MM][LL];
    __shared__ float sdsum[GG];

    stage_alpha(delta + b * TT, tau, g, lane, t0, sdt, sal, sdsum);

    float4 s[MM];
    #pragma unroll
    for (int m = 0; m < MM; m++) s[m] = make_float4(0.f, 0.f, 0.f, 0.f);

    const float4* xp = (const float4*)x + (b * TT + t0) * D4 + lane;
    #pragma unroll 4
    for (int i = 0; i < LL; i++) {
        const float4 xv = xp[i * D4];
        #pragma unroll
        for (int m = 0; m < MM; m++) {
            const float a = sal[g][m][i];
            s[m].x = fmaf(a, s[m].x - xv.x, xv.x);
            s[m].y = fmaf(a, s[m].y - xv.y, xv.y);
            s[m].z = fmaf(a, s[m].z - xv.z, xv.z);
            s[m].w = fmaf(a, s[m].w - xv.w, xv.w);
        }
    }

    const int base = (b * CC + c) * MM * D4 + lane;
    #pragma unroll
    for (int m = 0; m < MM; m++)
        ((float4*)g_send)[base + m * D4] = s[m];
    if (lane < MM)
        g_A[(b * CC + c) * MM + lane] = expf(-sdsum[g] / tau[lane]);
}

// ---------------------------------------------------------------------------
// Phase 2: sequential scan across chunks per (b,m,d):
//   s_in[c] = s;  s = A[c]*s + s_end[c].   L2-resident.
// ---------------------------------------------------------------------------
__global__ void __launch_bounds__(128) lc_phase2()
{
    const int idx = blockIdx.x * blockDim.x + threadIdx.x;  // (b*M+m)*D + d
    const int d  = idx % DD;
    const int bm = idx / DD;
    const int m  = bm % MM;
    const int b  = bm / MM;

    float s = 0.0f;
    #pragma unroll 8
    for (int c = 0; c < CC; c++) {
        const int base = ((b * CC + c) * MM + m) * DD + d;
        g_sin[base] = s;
        s = fmaf(g_A[(b * CC + c) * MM + m], s, g_send[base]);
    }
}

// ---------------------------------------------------------------------------
// Phase 3: re-scan each chunk from its true s_in and stream the output.
// Compute all 8 m-updates per t first, then store the 8 float4 as one
// front-batched burst (one contiguous 8KB (t,:,:) row per chunk-group step).
// ---------------------------------------------------------------------------
__global__ void __launch_bounds__(NTHR) lc_phase3(
    const float* __restrict__ x, const float* __restrict__ delta,
    const float* __restrict__ tau, float* __restrict__ out)
{
    const int b = blockIdx.y;
    const int tid = threadIdx.x;
    const int g = tid >> 6, lane = tid & 63;
    const int c = blockIdx.x * GG + g;
    const int t0 = c * LL;

    __shared__ float sdt[GG][LL];
    __shared__ float sal[GG][MM][LL];
    __shared__ float sdsum[GG];

    stage_alpha(delta + b * TT, tau, g, lane, t0, sdt, sal, sdsum);

    const int base = (b * CC + c) * MM * D4 + lane;
    float4 s[MM];
    #pragma unroll
    for (int m = 0; m < MM; m++)
        s[m] = ((const float4*)g_sin)[base + m * D4];

    const float4* xp = (const float4*)x + (b * TT + t0) * D4 + lane;
    float4* op = (float4*)out + (b * TT + t0) * (MM * D4) + lane;

    #pragma unroll 4
    for (int i = 0; i < LL; i++) {
        const float4 xv = xp[i * D4];
        #pragma unroll
        for (int m = 0; m < MM; m++) {
            const float a = sal[g][m][i];
            s[m].x = fmaf(a, s[m].x - xv.x, xv.x);
            s[m].y = fmaf(a, s[m].y - xv.y, xv.y);
            s[m].z = fmaf(a, s[m].z - xv.z, xv.z);
            s[m].w = fmaf(a, s[m].w - xv.w, xv.w);
        }
        float4* orow = op + i * (MM * D4);
        #pragma unroll
        for (int m = 0; m < MM; m++)
            orow[m * D4] = s[m];
    }
}

// ---------------------------------------------------------------------------
extern "C" void kernel_launch(void* const* d_in, const int* in_sizes, int n_in,
                              void* d_out, int out_size)
{
    const float* x     = (const float*)d_in[0];
    const float* delta = (const float*)d_in[1];
    const float* tau   = (const float*)d_in[2];
    float* out = (float*)d_out;

    dim3 grid(CC / GG, BB);
    lc_phase1<<<grid, NTHR>>>(x, delta, tau);
    lc_phase2<<<128, 128>>>();
    lc_phase3<<<grid, NTHR>>>(x, delta, tau, out);
}